// round 1
// baseline (speedup 1.0000x reference)
#include <cuda_runtime.h>
#include <cuda_bf16.h>

// ---------------- problem dims ----------------
#define BQ 8
#define LQ 2048
#define MQ (BQ*LQ)      // 16384 tokens
#define DQ 512          // d_model
#define EQ 1024         // d_inner
#define SQ 16           // d_state
#define GQ 48           // 3*d_state

// ---------------- scratch (__device__ globals; no allocation allowed) ----------------
__device__ __nv_bfloat16 g_xn[(size_t)MQ*DQ];       // LN output (GEMM1 A)
__device__ float         g_xin[(size_t)MQ*EQ];      // in_proj x_ branch (conv input)
__device__ __nv_bfloat16 g_siluz[(size_t)MQ*EQ];    // silu(z)
__device__ __nv_bfloat16 g_xc[(size_t)MQ*EQ];       // conv+silu output (GEMM2 A)
__device__ float         g_xg[(size_t)MQ*GQ];       // GRU input gates
__device__ float         g_h[(size_t)MQ*SQ];        // GRU hidden per step
__device__ __nv_bfloat16 g_ymid[(size_t)MQ*EQ];     // gated ssm output (GEMM3 A)
__device__ __nv_bfloat16 g_wA[2048*512];            // in_proj_w bf16
__device__ __nv_bfloat16 g_wG[128*1024];            // gru_w_ih bf16 (padded 48->128 rows)
__device__ __nv_bfloat16 g_wO[512*1024];            // out_proj_w bf16

// ---------------- helpers ----------------
__device__ __forceinline__ float tanh_fast(float x){
    float y; asm("tanh.approx.f32 %0, %1;" : "=f"(y) : "f"(x)); return y;
}
__device__ __forceinline__ float sigmoid_fast(float x){
    return fmaf(0.5f, tanh_fast(0.5f*x), 0.5f);
}
__device__ __forceinline__ float silu_fast(float x){ return x * sigmoid_fast(x); }

__device__ __forceinline__ unsigned smem_u32(const void* p){
    return (unsigned)__cvta_generic_to_shared(p);
}
__device__ __forceinline__ void ldm_x4(unsigned& r0, unsigned& r1, unsigned& r2, unsigned& r3, unsigned a){
    asm volatile("ldmatrix.sync.aligned.m8n8.x4.shared.b16 {%0,%1,%2,%3}, [%4];"
        : "=r"(r0),"=r"(r1),"=r"(r2),"=r"(r3) : "r"(a));
}
__device__ __forceinline__ void ldm_x2(unsigned& r0, unsigned& r1, unsigned a){
    asm volatile("ldmatrix.sync.aligned.m8n8.x2.shared.b16 {%0,%1}, [%2];"
        : "=r"(r0),"=r"(r1) : "r"(a));
}
__device__ __forceinline__ void mma_bf16(float c[4], unsigned a0,unsigned a1,unsigned a2,unsigned a3,
                                         unsigned b0, unsigned b1){
    asm volatile("mma.sync.aligned.m16n8k16.row.col.f32.bf16.bf16.f32 "
        "{%0,%1,%2,%3}, {%4,%5,%6,%7}, {%8,%9}, {%0,%1,%2,%3};"
        : "+f"(c[0]),"+f"(c[1]),"+f"(c[2]),"+f"(c[3])
        : "r"(a0),"r"(a1),"r"(a2),"r"(a3),"r"(b0),"r"(b1));
}

// ---------------- weight conversion (fp32 -> bf16, one pass) ----------------
__global__ void k_convert_all(const float* __restrict__ wa, const float* __restrict__ wg,
                              const float* __restrict__ wo){
    const int NA = 2048*512;        // in_proj
    const int NG = 128*1024;        // gru padded
    const int NO = 512*1024;        // out_proj
    int i = blockIdx.x*blockDim.x + threadIdx.x;
    if (i < NA){
        g_wA[i] = __float2bfloat16(wa[i]);
    } else if (i < NA + NG){
        int j = i - NA;
        g_wG[j] = (j < 48*1024) ? __float2bfloat16(wg[j]) : __float2bfloat16(0.f);
    } else if (i < NA + NG + NO){
        int j = i - NA - NG;
        g_wO[j] = __float2bfloat16(wo[j]);
    }
}

// ---------------- LayerNorm: [MQ,512] rows, 128 threads/row ----------------
__global__ __launch_bounds__(128) void k_ln(const float* __restrict__ x,
                                            const float* __restrict__ w,
                                            const float* __restrict__ bb){
    int row = blockIdx.x;
    int tid = threadIdx.x;
    const float4* xr = (const float4*)(x + (size_t)row*DQ);
    float4 v = xr[tid];
    float s  = v.x + v.y + v.z + v.w;
    float ss = fmaf(v.x,v.x, fmaf(v.y,v.y, fmaf(v.z,v.z, v.w*v.w)));
    #pragma unroll
    for (int o=16;o;o>>=1){ s += __shfl_xor_sync(~0u,s,o); ss += __shfl_xor_sync(~0u,ss,o); }
    __shared__ float rs[4], rss[4];
    __shared__ float smu, srstd;
    int wid = tid>>5;
    if ((tid&31)==0){ rs[wid]=s; rss[wid]=ss; }
    __syncthreads();
    if (tid==0){
        float S = rs[0]+rs[1]+rs[2]+rs[3];
        float SS= rss[0]+rss[1]+rss[2]+rss[3];
        float mu = S * (1.f/512.f);
        float var = SS * (1.f/512.f) - mu*mu;
        smu = mu; srstd = rsqrtf(var + 1e-5f);
    }
    __syncthreads();
    float mu = smu, rstd = srstd;
    float4 w4 = ((const float4*)w)[tid];
    float4 b4 = ((const float4*)bb)[tid];
    float y0 = fmaf((v.x-mu)*rstd, w4.x, b4.x);
    float y1 = fmaf((v.y-mu)*rstd, w4.y, b4.y);
    float y2 = fmaf((v.z-mu)*rstd, w4.z, b4.z);
    float y3 = fmaf((v.w-mu)*rstd, w4.w, b4.w);
    __nv_bfloat162* dst = (__nv_bfloat162*)(g_xn + (size_t)row*DQ);
    dst[tid*2]   = __floats2bfloat162_rn(y0, y1);
    dst[tid*2+1] = __floats2bfloat162_rn(y2, y3);
}

// ---------------- bf16 mma GEMM: C[M,N] = A[M,K] @ B[N,K]^T ----------------
// BM=128, BN=128, BK=32, 256 threads, 8 warps (2x4), warp tile 64x32
// MODE 0: in_proj  (A=g_xn,   B=g_wA, K=512 ; epilogue: x_ f32 / silu(z) bf16)
// MODE 1: gru_ih   (A=g_xc,   B=g_wG, K=1024; epilogue: xg f32, cols<48)
// MODE 2: out_proj (A=g_ymid, B=g_wO, K=1024; epilogue: +bias +residual -> out f32)
template<int MODE>
__global__ __launch_bounds__(256) void k_gemm(const float* __restrict__ bias,
                                              const float* __restrict__ resid,
                                              float* __restrict__ outf){
    const __nv_bfloat16* __restrict__ A;
    const __nv_bfloat16* __restrict__ Bw;
    int K;
    if constexpr (MODE==0){ A = g_xn;   Bw = g_wA; K = 512;  }
    if constexpr (MODE==1){ A = g_xc;   Bw = g_wG; K = 1024; }
    if constexpr (MODE==2){ A = g_ymid; Bw = g_wO; K = 1024; }

    __shared__ __align__(16) __nv_bfloat16 Asm[128][40];
    __shared__ __align__(16) __nv_bfloat16 Bsm[128][40];

    const int tid  = threadIdx.x;
    const int lane = tid & 31, warp = tid >> 5;
    const int wm = warp >> 2, wn = warp & 3;          // 2 x 4 warp grid
    const int mBlk = blockIdx.y * 128, nBlk = blockIdx.x * 128;

    float acc[4][4][4];
    #pragma unroll
    for (int mt=0;mt<4;mt++)
        #pragma unroll
        for (int nt=0;nt<4;nt++)
            #pragma unroll
            for (int q=0;q<4;q++) acc[mt][nt][q] = 0.f;

    const int nK = K >> 5;
    const int row0 = tid >> 2;          // 0..63 step covers via 2 iters
    const int ch   = tid & 3;
    for (int kb = 0; kb < nK; kb++){
        #pragma unroll
        for (int it=0; it<2; it++){
            int row = row0 + it*64;
            const uint4* pa = (const uint4*)(A  + (size_t)(mBlk+row)*K + kb*32 + ch*8);
            *(uint4*)&Asm[row][ch*8] = *pa;
            const uint4* pb = (const uint4*)(Bw + (size_t)(nBlk+row)*K + kb*32 + ch*8);
            *(uint4*)&Bsm[row][ch*8] = *pb;
        }
        __syncthreads();
        #pragma unroll
        for (int k2=0;k2<2;k2++){
            unsigned a[4][4], b[4][2];
            #pragma unroll
            for (int mt=0;mt<4;mt++){
                unsigned addr = smem_u32(&Asm[wm*64 + mt*16 + (lane&15)][k2*16 + (lane>>4)*8]);
                ldm_x4(a[mt][0],a[mt][1],a[mt][2],a[mt][3], addr);
            }
            #pragma unroll
            for (int nt=0;nt<4;nt++){
                unsigned addr = smem_u32(&Bsm[wn*32 + nt*8 + (lane&7)][k2*16 + ((lane>>3)&1)*8]);
                ldm_x2(b[nt][0],b[nt][1], addr);
            }
            #pragma unroll
            for (int mt=0;mt<4;mt++)
                #pragma unroll
                for (int nt=0;nt<4;nt++)
                    mma_bf16(acc[mt][nt], a[mt][0],a[mt][1],a[mt][2],a[mt][3], b[nt][0],b[nt][1]);
        }
        __syncthreads();
    }

    // epilogue
    #pragma unroll
    for (int mt=0;mt<4;mt++){
        #pragma unroll
        for (int nt=0;nt<4;nt++){
            int rowb = mBlk + wm*64 + mt*16 + (lane>>2);
            int col  = nBlk + wn*32 + nt*8 + (lane&3)*2;
            #pragma unroll
            for (int half=0; half<2; half++){
                int r = rowb + half*8;
                float v0 = acc[mt][nt][half*2+0];
                float v1 = acc[mt][nt][half*2+1];
                if constexpr (MODE==0){
                    v0 += bias[col]; v1 += bias[col+1];
                    if (col < 1024){
                        g_xin[(size_t)r*1024 + col]   = v0;
                        g_xin[(size_t)r*1024 + col+1] = v1;
                    } else {
                        g_siluz[(size_t)r*1024 + col-1024]   = __float2bfloat16(silu_fast(v0));
                        g_siluz[(size_t)r*1024 + col-1024+1] = __float2bfloat16(silu_fast(v1));
                    }
                }
                if constexpr (MODE==1){
                    if (col < GQ)   g_xg[(size_t)r*GQ + col]   = v0 + bias[col];
                    if (col+1 < GQ) g_xg[(size_t)r*GQ + col+1] = v1 + bias[col+1];
                }
                if constexpr (MODE==2){
                    size_t o = (size_t)r*512 + col;
                    outf[o]   = v0 + bias[col]   + resid[o];
                    outf[o+1] = v1 + bias[col+1] + resid[o+1];
                }
            }
        }
    }
}

// ---------------- depthwise conv1d (k=3, pad=1) + SiLU -> bf16 ----------------
__global__ void k_conv(const float* __restrict__ cw, const float* __restrict__ cb){
    int i = blockIdx.x*blockDim.x + threadIdx.x;
    if (i >= MQ*EQ) return;
    int e = i & (EQ-1);
    int m = i >> 10;
    int l = m & (LQ-1);
    float mid   = g_xin[i];
    float left  = (l > 0)      ? g_xin[i - EQ] : 0.f;
    float right = (l < LQ-1)   ? g_xin[i + EQ] : 0.f;
    float w0 = cw[e*3+0], w1 = cw[e*3+1], w2 = cw[e*3+2];
    float v = fmaf(w0, left, fmaf(w1, mid, fmaf(w2, right, cb[e])));
    g_xc[i] = __float2bfloat16(silu_fast(v));
}

// ---------------- GRU scan: 1 warp per batch, serial over L ----------------
__device__ __forceinline__ float dot16(const float (&w)[16], const float (&h)[16]){
    float a0=0.f,a1=0.f,a2=0.f,a3=0.f;
    #pragma unroll
    for (int k=0;k<16;k+=4){
        a0 = fmaf(w[k],  h[k],  a0);
        a1 = fmaf(w[k+1],h[k+1],a1);
        a2 = fmaf(w[k+2],h[k+2],a2);
        a3 = fmaf(w[k+3],h[k+3],a3);
    }
    return (a0+a1)+(a2+a3);
}

__global__ __launch_bounds__(32) void k_gru(const float* __restrict__ Whh,
                                            const float* __restrict__ bhh){
    const int b = blockIdx.x;
    const int lane = threadIdx.x;
    __shared__ float sh[32*GQ];   // 32-step chunk of xg

    float Wr[16], Wz[16], Wn[16];
    float br=0.f, bz=0.f, bn=0.f;
    if (lane < 16){
        #pragma unroll
        for (int k=0;k<16;k++){
            Wr[k] = Whh[lane*16 + k];
            Wz[k] = Whh[(16+lane)*16 + k];
            Wn[k] = Whh[(32+lane)*16 + k];
        }
        br = bhh[lane]; bz = bhh[16+lane]; bn = bhh[32+lane];
    } else {
        #pragma unroll
        for (int k=0;k<16;k++){ Wr[k]=0.f; Wz[k]=0.f; Wn[k]=0.f; }
    }

    float h[16];
    #pragma unroll
    for (int k=0;k<16;k++) h[k] = 0.f;
    float hi = 0.f;

    const float* xb = g_xg + (size_t)b*LQ*GQ;
    float*       hb = g_h  + (size_t)b*LQ*SQ;

    for (int c=0; c<LQ/32; c++){
        __syncwarp();
        const float4* src = (const float4*)(xb + (size_t)c*32*GQ);
        float4* dst = (float4*)sh;
        #pragma unroll
        for (int j=0;j<12;j++) dst[lane + 32*j] = src[lane + 32*j];
        __syncwarp();
        #pragma unroll 4
        for (int t=0;t<32;t++){
            const float* s = sh + t*GQ;
            float xr=0.f, xz=0.f, xn=0.f;
            if (lane < 16){ xr = s[lane]; xz = s[16+lane]; xn = s[32+lane]; }
            float hr = dot16(Wr, h) + br;
            float hz = dot16(Wz, h) + bz;
            float hn = dot16(Wn, h) + bn;
            float r  = sigmoid_fast(xr + hr);
            float z  = sigmoid_fast(xz + hz);
            float n  = tanh_fast(fmaf(r, hn, xn));
            float hnew = fmaf(z, hi - n, n);
            #pragma unroll
            for (int k=0;k<16;k++) h[k] = __shfl_sync(0xffffffffu, hnew, k);
            hi = hnew;
            if (lane < 16) hb[(size_t)(c*32+t)*SQ + lane] = hnew;
        }
    }
}

// ---------------- ssm_proj (K=16) + gate by silu(z) -> bf16 ----------------
__global__ void k_ssm(const float* __restrict__ W, const float* __restrict__ bias){
    int i = blockIdx.x*blockDim.x + threadIdx.x;
    if (i >= MQ*EQ) return;
    int e = i & (EQ-1);
    int m = i >> 10;
    const float* hr = g_h + (size_t)m*SQ;
    const float* wr = W   + (size_t)e*SQ;
    float acc = bias[e];
    #pragma unroll
    for (int k=0;k<16;k++) acc = fmaf(__ldg(hr+k), __ldg(wr+k), acc);
    float sz = __bfloat162float(g_siluz[i]);
    g_ymid[i] = __float2bfloat16(acc * sz);
}

// ---------------- launch ----------------
extern "C" void kernel_launch(void* const* d_in, const int* in_sizes, int n_in,
                              void* d_out, int out_size){
    const float* x        = (const float*)d_in[0];
    const float* norm_w   = (const float*)d_in[1];
    const float* norm_b   = (const float*)d_in[2];
    const float* in_proj_w= (const float*)d_in[3];
    const float* in_proj_b= (const float*)d_in[4];
    const float* conv_w   = (const float*)d_in[5];
    const float* conv_b   = (const float*)d_in[6];
    const float* gru_w_ih = (const float*)d_in[7];
    const float* gru_w_hh = (const float*)d_in[8];
    const float* gru_b_ih = (const float*)d_in[9];
    const float* gru_b_hh = (const float*)d_in[10];
    const float* ssm_w    = (const float*)d_in[11];
    const float* ssm_b    = (const float*)d_in[12];
    const float* out_w    = (const float*)d_in[13];
    const float* out_b    = (const float*)d_in[14];
    float* out = (float*)d_out;

    const int NCVT = 2048*512 + 128*1024 + 512*1024;
    k_convert_all<<<(NCVT+255)/256, 256>>>(in_proj_w, gru_w_ih, out_w);

    k_ln<<<MQ, 128>>>(x, norm_w, norm_b);

    k_gemm<0><<<dim3(2048/128, MQ/128), 256>>>(in_proj_b, nullptr, nullptr);

    k_conv<<<(MQ*EQ+255)/256, 256>>>(conv_w, conv_b);

    k_gemm<1><<<dim3(1, MQ/128), 256>>>(gru_b_ih, nullptr, nullptr);

    k_gru<<<BQ, 32>>>(gru_w_hh, gru_b_hh);

    k_ssm<<<(MQ*EQ+255)/256, 256>>>(ssm_w, ssm_b);

    k_gemm<2><<<dim3(512/128, MQ/128), 256>>>(out_b, x, out);
}

// round 2
// speedup vs baseline: 1.3550x; 1.3550x over previous
#include <cuda_runtime.h>
#include <cuda_bf16.h>

// ---------------- problem dims ----------------
#define BQ 8
#define LQ 2048
#define MQ (BQ*LQ)      // 16384 tokens
#define DQ 512          // d_model
#define EQ 1024         // d_inner
#define SQ 16           // d_state
#define GQ 48           // 3*d_state

// ---------------- scratch (__device__ globals; no allocation allowed) ----------------
__device__ __nv_bfloat16 g_xn[(size_t)MQ*DQ];       // LN output (GEMM1 A)
__device__ __nv_bfloat16 g_xin[(size_t)MQ*EQ];      // in_proj x_ branch (conv input), bf16
__device__ __nv_bfloat16 g_siluz[(size_t)MQ*EQ];    // silu(z)
__device__ __nv_bfloat16 g_xc[(size_t)MQ*EQ];       // conv+silu output (GEMM2 A)
__device__ float         g_xg[(size_t)MQ*GQ];       // GRU input gates
__device__ float         g_h[(size_t)MQ*SQ];        // GRU hidden per step
__device__ __nv_bfloat16 g_ymid[(size_t)MQ*EQ];     // gated ssm output (GEMM3 A)
__device__ __nv_bfloat16 g_wA[2048*512];            // in_proj_w bf16
__device__ __nv_bfloat16 g_wG[128*1024];            // gru_w_ih bf16 (padded 48->128 rows)
__device__ __nv_bfloat16 g_wO[512*1024];            // out_proj_w bf16

// ---------------- helpers ----------------
__device__ __forceinline__ float tanh_fast(float x){
    float y; asm("tanh.approx.f32 %0, %1;" : "=f"(y) : "f"(x)); return y;
}
__device__ __forceinline__ float sigmoid_fast(float x){
    return fmaf(0.5f, tanh_fast(0.5f*x), 0.5f);
}
__device__ __forceinline__ float silu_fast(float x){ return x * sigmoid_fast(x); }

__device__ __forceinline__ unsigned smem_u32(const void* p){
    return (unsigned)__cvta_generic_to_shared(p);
}
__device__ __forceinline__ void ldm_x4(unsigned& r0, unsigned& r1, unsigned& r2, unsigned& r3, unsigned a){
    asm volatile("ldmatrix.sync.aligned.m8n8.x4.shared.b16 {%0,%1,%2,%3}, [%4];"
        : "=r"(r0),"=r"(r1),"=r"(r2),"=r"(r3) : "r"(a));
}
__device__ __forceinline__ void ldm_x2(unsigned& r0, unsigned& r1, unsigned a){
    asm volatile("ldmatrix.sync.aligned.m8n8.x2.shared.b16 {%0,%1}, [%2];"
        : "=r"(r0),"=r"(r1) : "r"(a));
}
__device__ __forceinline__ void mma_bf16(float c[4], unsigned a0,unsigned a1,unsigned a2,unsigned a3,
                                         unsigned b0, unsigned b1){
    asm volatile("mma.sync.aligned.m16n8k16.row.col.f32.bf16.bf16.f32 "
        "{%0,%1,%2,%3}, {%4,%5,%6,%7}, {%8,%9}, {%0,%1,%2,%3};"
        : "+f"(c[0]),"+f"(c[1]),"+f"(c[2]),"+f"(c[3])
        : "r"(a0),"r"(a1),"r"(a2),"r"(a3),"r"(b0),"r"(b1));
}
__device__ __forceinline__ void cp16(unsigned sdst, const void* gsrc){
    asm volatile("cp.async.cg.shared.global [%0], [%1], 16;" :: "r"(sdst), "l"(gsrc));
}
__device__ __forceinline__ void cp_commit(){ asm volatile("cp.async.commit_group;" ::: "memory"); }
__device__ __forceinline__ void cp_wait0(){ asm volatile("cp.async.wait_group 0;" ::: "memory"); }
__device__ __forceinline__ void cp_wait1(){ asm volatile("cp.async.wait_group 1;" ::: "memory"); }

// ---------------- weight conversion (fp32 -> bf16, one pass) ----------------
__global__ void k_convert_all(const float* __restrict__ wa, const float* __restrict__ wg,
                              const float* __restrict__ wo){
    const int NA = 2048*512;
    const int NG = 128*1024;
    const int NO = 512*1024;
    int i = blockIdx.x*blockDim.x + threadIdx.x;
    if (i < NA){
        g_wA[i] = __float2bfloat16(wa[i]);
    } else if (i < NA + NG){
        int j = i - NA;
        g_wG[j] = (j < 48*1024) ? __float2bfloat16(wg[j]) : __float2bfloat16(0.f);
    } else if (i < NA + NG + NO){
        int j = i - NA - NG;
        g_wO[j] = __float2bfloat16(wo[j]);
    }
}

// ---------------- LayerNorm: [MQ,512] rows, 128 threads/row ----------------
__global__ __launch_bounds__(128) void k_ln(const float* __restrict__ x,
                                            const float* __restrict__ w,
                                            const float* __restrict__ bb){
    int row = blockIdx.x;
    int tid = threadIdx.x;
    const float4* xr = (const float4*)(x + (size_t)row*DQ);
    float4 v = xr[tid];
    float s  = v.x + v.y + v.z + v.w;
    float ss = fmaf(v.x,v.x, fmaf(v.y,v.y, fmaf(v.z,v.z, v.w*v.w)));
    #pragma unroll
    for (int o=16;o;o>>=1){ s += __shfl_xor_sync(~0u,s,o); ss += __shfl_xor_sync(~0u,ss,o); }
    __shared__ float rs[4], rss[4];
    __shared__ float smu, srstd;
    int wid = tid>>5;
    if ((tid&31)==0){ rs[wid]=s; rss[wid]=ss; }
    __syncthreads();
    if (tid==0){
        float S = rs[0]+rs[1]+rs[2]+rs[3];
        float SS= rss[0]+rss[1]+rss[2]+rss[3];
        float mu = S * (1.f/512.f);
        float var = SS * (1.f/512.f) - mu*mu;
        smu = mu; srstd = rsqrtf(var + 1e-5f);
    }
    __syncthreads();
    float mu = smu, rstd = srstd;
    float4 w4 = ((const float4*)w)[tid];
    float4 b4 = ((const float4*)bb)[tid];
    float y0 = fmaf((v.x-mu)*rstd, w4.x, b4.x);
    float y1 = fmaf((v.y-mu)*rstd, w4.y, b4.y);
    float y2 = fmaf((v.z-mu)*rstd, w4.z, b4.z);
    float y3 = fmaf((v.w-mu)*rstd, w4.w, b4.w);
    __nv_bfloat162* dst = (__nv_bfloat162*)(g_xn + (size_t)row*DQ);
    dst[tid*2]   = __floats2bfloat162_rn(y0, y1);
    dst[tid*2+1] = __floats2bfloat162_rn(y2, y3);
}

// ---------------- bf16 mma GEMM, cp.async double-buffered ----------------
// C[M,N] = A[M,K] @ B[N,K]^T. BM=128, BN=128, BK=32, 256 threads, warp tile 64x32.
// MODE 0: in_proj  (A=g_xn,   B=g_wA, K=512 ; epilogue: x_ bf16 / silu(z) bf16)
// MODE 1: gru_ih   (A=g_xc,   B=g_wG, K=1024; epilogue: xg f32, cols<48)
// MODE 2: out_proj (A=g_ymid, B=g_wO, K=1024; epilogue: +bias +residual -> out f32)
template<int MODE>
__global__ __launch_bounds__(256,2) void k_gemm(const float* __restrict__ bias,
                                                const float* __restrict__ resid,
                                                float* __restrict__ outf){
    const __nv_bfloat16* __restrict__ A;
    const __nv_bfloat16* __restrict__ Bw;
    int K;
    if constexpr (MODE==0){ A = g_xn;   Bw = g_wA; K = 512;  }
    if constexpr (MODE==1){ A = g_xc;   Bw = g_wG; K = 1024; }
    if constexpr (MODE==2){ A = g_ymid; Bw = g_wO; K = 1024; }

    // 80-byte row stride = 5 x 16B chunks: stride 5 mod 8 coprime -> ldmatrix conflict-free
    __shared__ __align__(16) __nv_bfloat16 Asm[2][128][40];
    __shared__ __align__(16) __nv_bfloat16 Bsm[2][128][40];

    const int tid  = threadIdx.x;
    const int lane = tid & 31, warp = tid >> 5;
    const int wm = warp >> 2, wn = warp & 3;          // 2 x 4 warp grid
    const int mBlk = blockIdx.y * 128, nBlk = blockIdx.x * 128;

    float acc[4][4][4];
    #pragma unroll
    for (int mt=0;mt<4;mt++)
        #pragma unroll
        for (int nt=0;nt<4;nt++)
            #pragma unroll
            for (int q=0;q<4;q++) acc[mt][nt][q] = 0.f;

    const int nK = K >> 5;
    const int lrow = tid >> 2;      // 0..63
    const int lch  = tid & 3;
    const __nv_bfloat16* gA0 = A  + (size_t)(mBlk + lrow)      * K + lch*8;
    const __nv_bfloat16* gA1 = A  + (size_t)(mBlk + lrow + 64) * K + lch*8;
    const __nv_bfloat16* gB0 = Bw + (size_t)(nBlk + lrow)      * K + lch*8;
    const __nv_bfloat16* gB1 = Bw + (size_t)(nBlk + lrow + 64) * K + lch*8;

    auto prefetch = [&](int kb, int s){
        unsigned da = smem_u32(&Asm[s][lrow][lch*8]);
        unsigned db = smem_u32(&Bsm[s][lrow][lch*8]);
        const int ko = kb*32;
        cp16(da,           gA0 + ko);
        cp16(da + 64*80,   gA1 + ko);
        cp16(db,           gB0 + ko);
        cp16(db + 64*80,   gB1 + ko);
        cp_commit();
    };

    prefetch(0, 0);

    for (int kb = 0; kb < nK; kb++){
        const int s = kb & 1;
        if (kb + 1 < nK){
            prefetch(kb+1, s^1);
            cp_wait1();
        } else {
            cp_wait0();
        }
        __syncthreads();

        #pragma unroll
        for (int k2=0;k2<2;k2++){
            unsigned a[4][4], b[4][2];
            #pragma unroll
            for (int mt=0;mt<4;mt++){
                unsigned addr = smem_u32(&Asm[s][wm*64 + mt*16 + (lane&15)][k2*16 + (lane>>4)*8]);
                ldm_x4(a[mt][0],a[mt][1],a[mt][2],a[mt][3], addr);
            }
            #pragma unroll
            for (int nt=0;nt<4;nt++){
                unsigned addr = smem_u32(&Bsm[s][wn*32 + nt*8 + (lane&7)][k2*16 + ((lane>>3)&1)*8]);
                ldm_x2(b[nt][0],b[nt][1], addr);
            }
            #pragma unroll
            for (int mt=0;mt<4;mt++)
                #pragma unroll
                for (int nt=0;nt<4;nt++)
                    mma_bf16(acc[mt][nt], a[mt][0],a[mt][1],a[mt][2],a[mt][3], b[nt][0],b[nt][1]);
        }
        __syncthreads();
    }

    // epilogue
    #pragma unroll
    for (int mt=0;mt<4;mt++){
        #pragma unroll
        for (int nt=0;nt<4;nt++){
            int rowb = mBlk + wm*64 + mt*16 + (lane>>2);
            int col  = nBlk + wn*32 + nt*8 + (lane&3)*2;
            #pragma unroll
            for (int half=0; half<2; half++){
                int r = rowb + half*8;
                float v0 = acc[mt][nt][half*2+0];
                float v1 = acc[mt][nt][half*2+1];
                if constexpr (MODE==0){
                    v0 += bias[col]; v1 += bias[col+1];
                    if (col < 1024){
                        *(__nv_bfloat162*)&g_xin[(size_t)r*1024 + col] = __floats2bfloat162_rn(v0, v1);
                    } else {
                        *(__nv_bfloat162*)&g_siluz[(size_t)r*1024 + col-1024] =
                            __floats2bfloat162_rn(silu_fast(v0), silu_fast(v1));
                    }
                }
                if constexpr (MODE==1){
                    if (col < GQ){
                        g_xg[(size_t)r*GQ + col]   = v0 + bias[col];
                        g_xg[(size_t)r*GQ + col+1] = v1 + bias[col+1];
                    }
                }
                if constexpr (MODE==2){
                    size_t o = (size_t)r*512 + col;
                    float2 rr = *(const float2*)&resid[o];
                    float2 ov; ov.x = v0 + bias[col] + rr.x; ov.y = v1 + bias[col+1] + rr.y;
                    *(float2*)&outf[o] = ov;
                }
            }
        }
    }
}

// ---------------- depthwise conv1d (k=3, pad=1) + SiLU, 8 elems/thread ----------------
__global__ __launch_bounds__(256) void k_conv(const float* __restrict__ cw, const float* __restrict__ cb){
    int v = blockIdx.x*blockDim.x + threadIdx.x;
    if (v >= MQ*(EQ/8)) return;
    int e8 = v & 127;            // which 8-wide group within E
    int m  = v >> 7;
    int l  = m & (LQ-1);
    const uint4* base = (const uint4*)g_xin;
    size_t idx = (size_t)m*128 + e8;
    uint4 mid4 = base[idx];
    uint4 zz; zz.x=zz.y=zz.z=zz.w=0u;  // 0x0000 bf16 pairs == 0.0f
    uint4 lf4 = (l > 0)      ? base[idx-128] : zz;
    uint4 rt4 = (l < LQ-1)   ? base[idx+128] : zz;

    float fm[8], fl[8], fr[8];
    {
        const __nv_bfloat162* pm = (const __nv_bfloat162*)&mid4;
        const __nv_bfloat162* pl = (const __nv_bfloat162*)&lf4;
        const __nv_bfloat162* pr = (const __nv_bfloat162*)&rt4;
        #pragma unroll
        for (int j=0;j<4;j++){
            float2 a = __bfloat1622float2(pm[j]); fm[2*j]=a.x; fm[2*j+1]=a.y;
            float2 b = __bfloat1622float2(pl[j]); fl[2*j]=b.x; fl[2*j+1]=b.y;
            float2 c = __bfloat1622float2(pr[j]); fr[2*j]=c.x; fr[2*j+1]=c.y;
        }
    }
    int e0 = e8*8;
    __nv_bfloat162 outp[4];
    #pragma unroll
    for (int j=0;j<4;j++){
        float o0, o1;
        #pragma unroll
        for (int q=0;q<2;q++){
            int jj = 2*j+q;
            int e = e0 + jj;
            float w0 = __ldg(cw + e*3+0), w1 = __ldg(cw + e*3+1), w2 = __ldg(cw + e*3+2);
            float val = fmaf(w0, fl[jj], fmaf(w1, fm[jj], fmaf(w2, fr[jj], __ldg(cb + e))));
            float so = silu_fast(val);
            if (q==0) o0 = so; else o1 = so;
        }
        outp[j] = __floats2bfloat162_rn(o0, o1);
    }
    *(uint4*)&g_xc[(size_t)m*EQ + e0] = *(uint4*)outp;
}

// ---------------- GRU scan: 1 warp per batch, serial over L ----------------
__device__ __forceinline__ float dot16(const float (&w)[16], const float (&h)[16]){
    float a0=0.f,a1=0.f,a2=0.f,a3=0.f,a4=0.f,a5=0.f,a6=0.f,a7=0.f;
    a0=fmaf(w[0],h[0],a0);   a1=fmaf(w[1],h[1],a1);   a2=fmaf(w[2],h[2],a2);   a3=fmaf(w[3],h[3],a3);
    a4=fmaf(w[4],h[4],a4);   a5=fmaf(w[5],h[5],a5);   a6=fmaf(w[6],h[6],a6);   a7=fmaf(w[7],h[7],a7);
    a0=fmaf(w[8],h[8],a0);   a1=fmaf(w[9],h[9],a1);   a2=fmaf(w[10],h[10],a2); a3=fmaf(w[11],h[11],a3);
    a4=fmaf(w[12],h[12],a4); a5=fmaf(w[13],h[13],a5); a6=fmaf(w[14],h[14],a6); a7=fmaf(w[15],h[15],a7);
    return ((a0+a1)+(a2+a3)) + ((a4+a5)+(a6+a7));
}

__global__ __launch_bounds__(32) void k_gru(const float* __restrict__ Whh,
                                            const float* __restrict__ bhh){
    const int b = blockIdx.x;
    const int lane = threadIdx.x;
    __shared__ float sh[32*GQ];   // 32-step chunk of xg

    float Wr[16], Wz[16], Wn[16];
    float br=0.f, bz=0.f, bn=0.f;
    if (lane < 16){
        #pragma unroll
        for (int k=0;k<16;k++){
            Wr[k] = Whh[lane*16 + k];
            Wz[k] = Whh[(16+lane)*16 + k];
            Wn[k] = Whh[(32+lane)*16 + k];
        }
        br = bhh[lane]; bz = bhh[16+lane]; bn = bhh[32+lane];
    } else {
        #pragma unroll
        for (int k=0;k<16;k++){ Wr[k]=0.f; Wz[k]=0.f; Wn[k]=0.f; }
    }

    float h[16];
    #pragma unroll
    for (int k=0;k<16;k++) h[k] = 0.f;
    float hi = 0.f;

    const float* xb = g_xg + (size_t)b*LQ*GQ;
    float*       hb = g_h  + (size_t)b*LQ*SQ;

    for (int c=0; c<LQ/32; c++){
        __syncwarp();
        const float4* src = (const float4*)(xb + (size_t)c*32*GQ);
        float4* dst = (float4*)sh;
        #pragma unroll
        for (int j=0;j<12;j++) dst[lane + 32*j] = src[lane + 32*j];
        __syncwarp();
        #pragma unroll 4
        for (int t=0;t<32;t++){
            const float* s = sh + t*GQ;
            float xr=0.f, xz=0.f, xn=0.f;
            if (lane < 16){ xr = s[lane]; xz = s[16+lane]; xn = s[32+lane]; }
            float hr = dot16(Wr, h) + br;
            float hz = dot16(Wz, h) + bz;
            float hn = dot16(Wn, h) + bn;
            float r  = sigmoid_fast(xr + hr);
            float z  = sigmoid_fast(xz + hz);
            float n  = tanh_fast(fmaf(r, hn, xn));
            float hnew = fmaf(z, hi - n, n);
            #pragma unroll
            for (int k=0;k<16;k++) h[k] = __shfl_sync(0xffffffffu, hnew, k);
            hi = hnew;
            if (lane < 16) hb[(size_t)(c*32+t)*SQ + lane] = hnew;
        }
    }
}

// ---------------- ssm_proj (K=16) + gate by silu(z), 8 elems/thread ----------------
__global__ __launch_bounds__(256) void k_ssm(const float* __restrict__ W, const float* __restrict__ bias){
    int v = blockIdx.x*blockDim.x + threadIdx.x;
    if (v >= MQ*(EQ/8)) return;
    int e8 = v & 127;
    int m  = v >> 7;
    int e0 = e8*8;

    float h[16];
    {
        const float4* hv = (const float4*)(g_h + (size_t)m*SQ);
        #pragma unroll
        for (int j=0;j<4;j++){
            float4 t = __ldg(hv + j);
            h[4*j]=t.x; h[4*j+1]=t.y; h[4*j+2]=t.z; h[4*j+3]=t.w;
        }
    }
    uint4 sz4 = *(const uint4*)&g_siluz[(size_t)m*EQ + e0];
    const __nv_bfloat162* szp = (const __nv_bfloat162*)&sz4;

    __nv_bfloat162 outp[4];
    #pragma unroll
    for (int j=0;j<4;j++){
        float o[2];
        #pragma unroll
        for (int q=0;q<2;q++){
            int e = e0 + 2*j + q;
            const float4* wr = (const float4*)(W + (size_t)e*SQ);
            float acc = __ldg(bias + e);
            #pragma unroll
            for (int p=0;p<4;p++){
                float4 w4 = __ldg(wr + p);
                acc = fmaf(w4.x, h[4*p],   acc);
                acc = fmaf(w4.y, h[4*p+1], acc);
                acc = fmaf(w4.z, h[4*p+2], acc);
                acc = fmaf(w4.w, h[4*p+3], acc);
            }
            o[q] = acc;
        }
        float2 szf = __bfloat1622float2(szp[j]);
        outp[j] = __floats2bfloat162_rn(o[0]*szf.x, o[1]*szf.y);
    }
    *(uint4*)&g_ymid[(size_t)m*EQ + e0] = *(uint4*)outp;
}

// ---------------- launch ----------------
extern "C" void kernel_launch(void* const* d_in, const int* in_sizes, int n_in,
                              void* d_out, int out_size){
    const float* x        = (const float*)d_in[0];
    const float* norm_w   = (const float*)d_in[1];
    const float* norm_b   = (const float*)d_in[2];
    const float* in_proj_w= (const float*)d_in[3];
    const float* in_proj_b= (const float*)d_in[4];
    const float* conv_w   = (const float*)d_in[5];
    const float* conv_b   = (const float*)d_in[6];
    const float* gru_w_ih = (const float*)d_in[7];
    const float* gru_w_hh = (const float*)d_in[8];
    const float* gru_b_ih = (const float*)d_in[9];
    const float* gru_b_hh = (const float*)d_in[10];
    const float* ssm_w    = (const float*)d_in[11];
    const float* ssm_b    = (const float*)d_in[12];
    const float* out_w    = (const float*)d_in[13];
    const float* out_b    = (const float*)d_in[14];
    float* out = (float*)d_out;

    const int NCVT = 2048*512 + 128*1024 + 512*1024;
    k_convert_all<<<(NCVT+255)/256, 256>>>(in_proj_w, gru_w_ih, out_w);

    k_ln<<<MQ, 128>>>(x, norm_w, norm_b);

    k_gemm<0><<<dim3(2048/128, MQ/128), 256>>>(in_proj_b, nullptr, nullptr);

    k_conv<<<(MQ*(EQ/8)+255)/256, 256>>>(conv_w, conv_b);

    k_gemm<1><<<dim3(1, MQ/128), 256>>>(gru_b_ih, nullptr, nullptr);

    k_gru<<<BQ, 32>>>(gru_w_hh, gru_b_hh);

    k_ssm<<<(MQ*(EQ/8)+255)/256, 256>>>(ssm_w, ssm_b);

    k_gemm<2><<<dim3(512/128, MQ/128), 256>>>(out_b, x, out);
}

// round 3
// speedup vs baseline: 1.4538x; 1.0729x over previous
#include <cuda_runtime.h>
#include <cuda_bf16.h>

// ---------------- problem dims ----------------
#define BQ 8
#define LQ 2048
#define MQ (BQ*LQ)      // 16384 tokens
#define DQ 512          // d_model
#define EQ 1024         // d_inner
#define SQ 16           // d_state
#define GQ 48           // 3*d_state

// ---------------- scratch ----------------
__device__ __nv_bfloat16 g_xn[(size_t)MQ*DQ];
__device__ __nv_bfloat16 g_xin[(size_t)MQ*EQ];
__device__ __nv_bfloat16 g_siluz[(size_t)MQ*EQ];
__device__ __nv_bfloat16 g_xc[(size_t)MQ*EQ];
__device__ float         g_xg[(size_t)MQ*GQ];
__device__ float         g_h[(size_t)MQ*SQ];
__device__ __nv_bfloat16 g_ymid[(size_t)MQ*EQ];
__device__ __nv_bfloat16 g_wA[2048*512];
__device__ __nv_bfloat16 g_wG[128*1024];
__device__ __nv_bfloat16 g_wO[512*1024];

// ---------------- helpers ----------------
__device__ __forceinline__ float tanh_fast(float x){
    float y; asm("tanh.approx.f32 %0, %1;" : "=f"(y) : "f"(x)); return y;
}
__device__ __forceinline__ float sigmoid_fast(float x){
    return fmaf(0.5f, tanh_fast(0.5f*x), 0.5f);
}
__device__ __forceinline__ float silu_fast(float x){ return x * sigmoid_fast(x); }

__device__ __forceinline__ unsigned smem_u32(const void* p){
    return (unsigned)__cvta_generic_to_shared(p);
}
__device__ __forceinline__ void ldm_x4(unsigned& r0, unsigned& r1, unsigned& r2, unsigned& r3, unsigned a){
    asm volatile("ldmatrix.sync.aligned.m8n8.x4.shared.b16 {%0,%1,%2,%3}, [%4];"
        : "=r"(r0),"=r"(r1),"=r"(r2),"=r"(r3) : "r"(a));
}
__device__ __forceinline__ void ldm_x2(unsigned& r0, unsigned& r1, unsigned a){
    asm volatile("ldmatrix.sync.aligned.m8n8.x2.shared.b16 {%0,%1}, [%2];"
        : "=r"(r0),"=r"(r1) : "r"(a));
}
__device__ __forceinline__ void mma_bf16(float c[4], unsigned a0,unsigned a1,unsigned a2,unsigned a3,
                                         unsigned b0, unsigned b1){
    asm volatile("mma.sync.aligned.m16n8k16.row.col.f32.bf16.bf16.f32 "
        "{%0,%1,%2,%3}, {%4,%5,%6,%7}, {%8,%9}, {%0,%1,%2,%3};"
        : "+f"(c[0]),"+f"(c[1]),"+f"(c[2]),"+f"(c[3])
        : "r"(a0),"r"(a1),"r"(a2),"r"(a3),"r"(b0),"r"(b1));
}
__device__ __forceinline__ void cp16(unsigned sdst, const void* gsrc){
    asm volatile("cp.async.cg.shared.global [%0], [%1], 16;" :: "r"(sdst), "l"(gsrc));
}
__device__ __forceinline__ void cp_commit(){ asm volatile("cp.async.commit_group;" ::: "memory"); }
__device__ __forceinline__ void cp_wait1(){ asm volatile("cp.async.wait_group 1;" ::: "memory"); }

// ---------------- weight conversion (vectorized) ----------------
__global__ __launch_bounds__(256) void k_convert_all(const float* __restrict__ wa,
                                                     const float* __restrict__ wg,
                                                     const float* __restrict__ wo){
    const int NA4 = (2048*512)/4, NG4 = (128*1024)/4, NO4 = (512*1024)/4;
    int i = blockIdx.x*blockDim.x + threadIdx.x;
    float4 v; __nv_bfloat16* dst;
    if (i < NA4){
        v = __ldg((const float4*)wa + i);
        dst = g_wA + 4*(size_t)i;
    } else if (i < NA4 + NG4){
        int j = i - NA4;
        if (4*j < 48*1024) v = __ldg((const float4*)wg + j);
        else { v.x=v.y=v.z=v.w=0.f; }
        dst = g_wG + 4*(size_t)j;
    } else if (i < NA4 + NG4 + NO4){
        int j = i - NA4 - NG4;
        v = __ldg((const float4*)wo + j);
        dst = g_wO + 4*(size_t)j;
    } else return;
    __nv_bfloat162 p0 = __floats2bfloat162_rn(v.x, v.y);
    __nv_bfloat162 p1 = __floats2bfloat162_rn(v.z, v.w);
    uint2 u; u.x = *(unsigned*)&p0; u.y = *(unsigned*)&p1;
    *(uint2*)dst = u;
}

// ---------------- LayerNorm ----------------
__global__ __launch_bounds__(128) void k_ln(const float* __restrict__ x,
                                            const float* __restrict__ w,
                                            const float* __restrict__ bb){
    int row = blockIdx.x;
    int tid = threadIdx.x;
    const float4* xr = (const float4*)(x + (size_t)row*DQ);
    float4 v = xr[tid];
    float s  = v.x + v.y + v.z + v.w;
    float ss = fmaf(v.x,v.x, fmaf(v.y,v.y, fmaf(v.z,v.z, v.w*v.w)));
    #pragma unroll
    for (int o=16;o;o>>=1){ s += __shfl_xor_sync(~0u,s,o); ss += __shfl_xor_sync(~0u,ss,o); }
    __shared__ float rs[4], rss[4];
    __shared__ float smu, srstd;
    int wid = tid>>5;
    if ((tid&31)==0){ rs[wid]=s; rss[wid]=ss; }
    __syncthreads();
    if (tid==0){
        float S = rs[0]+rs[1]+rs[2]+rs[3];
        float SS= rss[0]+rss[1]+rss[2]+rss[3];
        float mu = S * (1.f/512.f);
        float var = SS * (1.f/512.f) - mu*mu;
        smu = mu; srstd = rsqrtf(var + 1e-5f);
    }
    __syncthreads();
    float mu = smu, rstd = srstd;
    float4 w4 = ((const float4*)w)[tid];
    float4 b4 = ((const float4*)bb)[tid];
    float y0 = fmaf((v.x-mu)*rstd, w4.x, b4.x);
    float y1 = fmaf((v.y-mu)*rstd, w4.y, b4.y);
    float y2 = fmaf((v.z-mu)*rstd, w4.z, b4.z);
    float y3 = fmaf((v.w-mu)*rstd, w4.w, b4.w);
    __nv_bfloat162* dst = (__nv_bfloat162*)(g_xn + (size_t)row*DQ);
    dst[tid*2]   = __floats2bfloat162_rn(y0, y1);
    dst[tid*2+1] = __floats2bfloat162_rn(y2, y3);
}

// ---------------- bf16 mma GEMM, 3-stage cp.async, 1 sync/iter ----------------
// C[M,N] = A[M,K] @ B[N,K]^T. BM=BN=128, BK=32, 256 thr, warp tile 64x32.
// Dynamic smem: A[3][128][40] then B[3][128][40] bf16 (61440 bytes).
#define GSTG 3
#define GROW 40           // elements per smem row (80B: 5x16B chunks, conflict-free)
#define GSTAGE_E (128*GROW)

template<int MODE>
__global__ __launch_bounds__(256,2) void k_gemm(const float* __restrict__ bias,
                                                const float* __restrict__ resid,
                                                float* __restrict__ outf){
    const __nv_bfloat16* __restrict__ A;
    const __nv_bfloat16* __restrict__ Bw;
    int K;
    if constexpr (MODE==0){ A = g_xn;   Bw = g_wA; K = 512;  }
    if constexpr (MODE==1){ A = g_xc;   Bw = g_wG; K = 1024; }
    if constexpr (MODE==2){ A = g_ymid; Bw = g_wO; K = 1024; }

    extern __shared__ __align__(16) __nv_bfloat16 dynsm[];
    __nv_bfloat16* As = dynsm;                    // [GSTG][128][GROW]
    __nv_bfloat16* Bs = dynsm + GSTG*GSTAGE_E;    // [GSTG][128][GROW]

    const int tid  = threadIdx.x;
    const int lane = tid & 31, warp = tid >> 5;
    const int wm = warp >> 2, wn = warp & 3;
    const int mBlk = blockIdx.y * 128, nBlk = blockIdx.x * 128;

    float acc[4][4][4];
    #pragma unroll
    for (int mt=0;mt<4;mt++)
        #pragma unroll
        for (int nt=0;nt<4;nt++)
            #pragma unroll
            for (int q=0;q<4;q++) acc[mt][nt][q] = 0.f;

    const int nK = K >> 5;
    const int lrow = tid >> 2;      // 0..63
    const int lch  = tid & 3;
    const __nv_bfloat16* gA0 = A  + (size_t)(mBlk + lrow)      * K + lch*8;
    const __nv_bfloat16* gB0 = Bw + (size_t)(nBlk + lrow)      * K + lch*8;
    const size_t strideA64 = (size_t)64 * K;

    auto prefetch = [&](int kb, int s){
        unsigned da = smem_u32(As + s*GSTAGE_E + lrow*GROW + lch*8);
        unsigned db = smem_u32(Bs + s*GSTAGE_E + lrow*GROW + lch*8);
        const int ko = kb*32;
        cp16(da,            gA0 + ko);
        cp16(da + 64*GROW*2, gA0 + strideA64 + ko);
        cp16(db,            gB0 + ko);
        cp16(db + 64*GROW*2, gB0 + strideA64 + ko);
        cp_commit();
    };

    prefetch(0, 0);
    prefetch(1, 1);

    int s = 0;
    for (int kb = 0; kb < nK; kb++){
        cp_wait1();
        __syncthreads();
        int pf = kb + 2;
        if (pf < nK){
            int sp = s + 2; if (sp >= GSTG) sp -= GSTG;
            prefetch(pf, sp);
        } else {
            cp_commit();
        }

        const __nv_bfloat16* Ab = As + s*GSTAGE_E;
        const __nv_bfloat16* Bb = Bs + s*GSTAGE_E;
        #pragma unroll
        for (int k2=0;k2<2;k2++){
            unsigned a[4][4], b[4][2];
            #pragma unroll
            for (int mt=0;mt<4;mt++){
                unsigned addr = smem_u32(Ab + (wm*64 + mt*16 + (lane&15))*GROW + k2*16 + (lane>>4)*8);
                ldm_x4(a[mt][0],a[mt][1],a[mt][2],a[mt][3], addr);
            }
            #pragma unroll
            for (int nt=0;nt<4;nt++){
                unsigned addr = smem_u32(Bb + (wn*32 + nt*8 + (lane&7))*GROW + k2*16 + ((lane>>3)&1)*8);
                ldm_x2(b[nt][0],b[nt][1], addr);
            }
            #pragma unroll
            for (int mt=0;mt<4;mt++)
                #pragma unroll
                for (int nt=0;nt<4;nt++)
                    mma_bf16(acc[mt][nt], a[mt][0],a[mt][1],a[mt][2],a[mt][3], b[nt][0],b[nt][1]);
        }
        s = (s==GSTG-1) ? 0 : s+1;
    }

    // epilogue
    #pragma unroll
    for (int mt=0;mt<4;mt++){
        #pragma unroll
        for (int nt=0;nt<4;nt++){
            int rowb = mBlk + wm*64 + mt*16 + (lane>>2);
            int col  = nBlk + wn*32 + nt*8 + (lane&3)*2;
            #pragma unroll
            for (int half=0; half<2; half++){
                int r = rowb + half*8;
                float v0 = acc[mt][nt][half*2+0];
                float v1 = acc[mt][nt][half*2+1];
                if constexpr (MODE==0){
                    v0 += bias[col]; v1 += bias[col+1];
                    if (col < 1024){
                        *(__nv_bfloat162*)&g_xin[(size_t)r*1024 + col] = __floats2bfloat162_rn(v0, v1);
                    } else {
                        *(__nv_bfloat162*)&g_siluz[(size_t)r*1024 + col-1024] =
                            __floats2bfloat162_rn(silu_fast(v0), silu_fast(v1));
                    }
                }
                if constexpr (MODE==1){
                    if (col < GQ){
                        g_xg[(size_t)r*GQ + col]   = v0 + bias[col];
                        g_xg[(size_t)r*GQ + col+1] = v1 + bias[col+1];
                    }
                }
                if constexpr (MODE==2){
                    size_t o = (size_t)r*512 + col;
                    float2 rr = *(const float2*)&resid[o];
                    float2 ov; ov.x = v0 + bias[col] + rr.x; ov.y = v1 + bias[col+1] + rr.y;
                    *(float2*)&outf[o] = ov;
                }
            }
        }
    }
}

// ---------------- depthwise conv1d (k=3, pad=1) + SiLU ----------------
// Each thread owns a fixed 8-wide e-group (weights in regs via float4), loops over 8 m's.
__global__ __launch_bounds__(256) void k_conv(const float* __restrict__ cw, const float* __restrict__ cb){
    const int tid = threadIdx.x;
    const int g = tid & 127;                 // e-group 0..127 (fixed across iters)
    const int e0 = g*8;
    // weights: cw[e0*3 .. e0*3+23] = 6 float4 (24g % 4 == 0 -> aligned)
    float wreg[24]; float breg[8];
    {
        const float4* wp = (const float4*)(cw + e0*3);
        #pragma unroll
        for (int j=0;j<6;j++){
            float4 t = __ldg(wp + j);
            wreg[4*j]=t.x; wreg[4*j+1]=t.y; wreg[4*j+2]=t.z; wreg[4*j+3]=t.w;
        }
        const float4* bp = (const float4*)(cb + e0);
        float4 t0 = __ldg(bp), t1 = __ldg(bp+1);
        breg[0]=t0.x;breg[1]=t0.y;breg[2]=t0.z;breg[3]=t0.w;
        breg[4]=t1.x;breg[5]=t1.y;breg[6]=t1.z;breg[7]=t1.w;
    }
    const uint4* base = (const uint4*)g_xin;
    uint4 zz; zz.x=zz.y=zz.z=zz.w=0u;

    #pragma unroll
    for (int it=0; it<8; it++){
        int v = blockIdx.x*2048 + it*256 + tid;
        int m = v >> 7;
        int l = m & (LQ-1);
        size_t idx = (size_t)m*128 + g;
        uint4 mid4 = base[idx];
        uint4 lf4 = (l > 0)      ? base[idx-128] : zz;
        uint4 rt4 = (l < LQ-1)   ? base[idx+128] : zz;

        const __nv_bfloat162* pm = (const __nv_bfloat162*)&mid4;
        const __nv_bfloat162* pl = (const __nv_bfloat162*)&lf4;
        const __nv_bfloat162* pr = (const __nv_bfloat162*)&rt4;
        __nv_bfloat162 outp[4];
        #pragma unroll
        for (int j=0;j<4;j++){
            float2 a = __bfloat1622float2(pm[j]);
            float2 bl= __bfloat1622float2(pl[j]);
            float2 cr= __bfloat1622float2(pr[j]);
            int jj = 2*j;
            float val0 = fmaf(wreg[jj*3+0], bl.x, fmaf(wreg[jj*3+1], a.x, fmaf(wreg[jj*3+2], cr.x, breg[jj])));
            float val1 = fmaf(wreg[jj*3+3], bl.y, fmaf(wreg[jj*3+4], a.y, fmaf(wreg[jj*3+5], cr.y, breg[jj+1])));
            outp[j] = __floats2bfloat162_rn(silu_fast(val0), silu_fast(val1));
        }
        *(uint4*)&g_xc[(size_t)m*EQ + e0] = *(uint4*)outp;
    }
}

// ---------------- GRU scan ----------------
__device__ __forceinline__ float dot16(const float (&w)[16], const float (&h)[16]){
    float a0=0.f,a1=0.f,a2=0.f,a3=0.f,a4=0.f,a5=0.f,a6=0.f,a7=0.f;
    a0=fmaf(w[0],h[0],a0);   a1=fmaf(w[1],h[1],a1);   a2=fmaf(w[2],h[2],a2);   a3=fmaf(w[3],h[3],a3);
    a4=fmaf(w[4],h[4],a4);   a5=fmaf(w[5],h[5],a5);   a6=fmaf(w[6],h[6],a6);   a7=fmaf(w[7],h[7],a7);
    a0=fmaf(w[8],h[8],a0);   a1=fmaf(w[9],h[9],a1);   a2=fmaf(w[10],h[10],a2); a3=fmaf(w[11],h[11],a3);
    a4=fmaf(w[12],h[12],a4); a5=fmaf(w[13],h[13],a5); a6=fmaf(w[14],h[14],a6); a7=fmaf(w[15],h[15],a7);
    return ((a0+a1)+(a2+a3)) + ((a4+a5)+(a6+a7));
}

__global__ __launch_bounds__(32) void k_gru(const float* __restrict__ Whh,
                                            const float* __restrict__ bhh){
    const int b = blockIdx.x;
    const int lane = threadIdx.x;
    __shared__ float sh[32*GQ];

    float Wr[16], Wz[16], Wn[16];
    float br=0.f, bz=0.f, bn=0.f;
    if (lane < 16){
        #pragma unroll
        for (int k=0;k<16;k++){
            Wr[k] = Whh[lane*16 + k];
            Wz[k] = Whh[(16+lane)*16 + k];
            Wn[k] = Whh[(32+lane)*16 + k];
        }
        br = bhh[lane]; bz = bhh[16+lane]; bn = bhh[32+lane];
    } else {
        #pragma unroll
        for (int k=0;k<16;k++){ Wr[k]=0.f; Wz[k]=0.f; Wn[k]=0.f; }
    }

    float h[16];
    #pragma unroll
    for (int k=0;k<16;k++) h[k] = 0.f;
    float hi = 0.f;

    const float* xb = g_xg + (size_t)b*LQ*GQ;
    float*       hb = g_h  + (size_t)b*LQ*SQ;

    for (int c=0; c<LQ/32; c++){
        __syncwarp();
        const float4* src = (const float4*)(xb + (size_t)c*32*GQ);
        float4* dst = (float4*)sh;
        #pragma unroll
        for (int j=0;j<12;j++) dst[lane + 32*j] = src[lane + 32*j];
        __syncwarp();
        #pragma unroll 4
        for (int t=0;t<32;t++){
            const float* sp = sh + t*GQ;
            float xr=0.f, xz=0.f, xn=0.f;
            if (lane < 16){ xr = sp[lane]; xz = sp[16+lane]; xn = sp[32+lane]; }
            float hr = dot16(Wr, h) + br;
            float hz = dot16(Wz, h) + bz;
            float hn = dot16(Wn, h) + bn;
            float r  = sigmoid_fast(xr + hr);
            float z  = sigmoid_fast(xz + hz);
            float n  = tanh_fast(fmaf(r, hn, xn));
            float hnew = fmaf(z, hi - n, n);
            #pragma unroll
            for (int k=0;k<16;k++) h[k] = __shfl_sync(0xffffffffu, hnew, k);
            hi = hnew;
            if (lane < 16) hb[(size_t)(c*32+t)*SQ + lane] = hnew;
        }
    }
}

// ---------------- ssm_proj (K=16) + gate by silu(z) ----------------
__global__ __launch_bounds__(256) void k_ssm(const float* __restrict__ W, const float* __restrict__ bias){
    int v = blockIdx.x*blockDim.x + threadIdx.x;
    if (v >= MQ*(EQ/8)) return;
    int e8 = v & 127;
    int m  = v >> 7;
    int e0 = e8*8;

    float h[16];
    {
        const float4* hv = (const float4*)(g_h + (size_t)m*SQ);
        #pragma unroll
        for (int j=0;j<4;j++){
            float4 t = __ldg(hv + j);
            h[4*j]=t.x; h[4*j+1]=t.y; h[4*j+2]=t.z; h[4*j+3]=t.w;
        }
    }
    uint4 sz4 = *(const uint4*)&g_siluz[(size_t)m*EQ + e0];
    const __nv_bfloat162* szp = (const __nv_bfloat162*)&sz4;

    __nv_bfloat162 outp[4];
    #pragma unroll
    for (int j=0;j<4;j++){
        float o[2];
        #pragma unroll
        for (int q=0;q<2;q++){
            int e = e0 + 2*j + q;
            const float4* wr = (const float4*)(W + (size_t)e*SQ);
            float acc = __ldg(bias + e);
            #pragma unroll
            for (int p=0;p<4;p++){
                float4 w4 = __ldg(wr + p);
                acc = fmaf(w4.x, h[4*p],   acc);
                acc = fmaf(w4.y, h[4*p+1], acc);
                acc = fmaf(w4.z, h[4*p+2], acc);
                acc = fmaf(w4.w, h[4*p+3], acc);
            }
            o[q] = acc;
        }
        float2 szf = __bfloat1622float2(szp[j]);
        outp[j] = __floats2bfloat162_rn(o[0]*szf.x, o[1]*szf.y);
    }
    *(uint4*)&g_ymid[(size_t)m*EQ + e0] = *(uint4*)outp;
}

// ---------------- launch ----------------
extern "C" void kernel_launch(void* const* d_in, const int* in_sizes, int n_in,
                              void* d_out, int out_size){
    const float* x        = (const float*)d_in[0];
    const float* norm_w   = (const float*)d_in[1];
    const float* norm_b   = (const float*)d_in[2];
    const float* in_proj_w= (const float*)d_in[3];
    const float* in_proj_b= (const float*)d_in[4];
    const float* conv_w   = (const float*)d_in[5];
    const float* conv_b   = (const float*)d_in[6];
    const float* gru_w_ih = (const float*)d_in[7];
    const float* gru_w_hh = (const float*)d_in[8];
    const float* gru_b_ih = (const float*)d_in[9];
    const float* gru_b_hh = (const float*)d_in[10];
    const float* ssm_w    = (const float*)d_in[11];
    const float* ssm_b    = (const float*)d_in[12];
    const float* out_w    = (const float*)d_in[13];
    const float* out_b    = (const float*)d_in[14];
    float* out = (float*)d_out;

    const int SMEM_GEMM = GSTG*GSTAGE_E*2*2;  // 61440 bytes
    static bool attr_done = false;
    if (!attr_done){
        cudaFuncSetAttribute(k_gemm<0>, cudaFuncAttributeMaxDynamicSharedMemorySize, SMEM_GEMM);
        cudaFuncSetAttribute(k_gemm<1>, cudaFuncAttributeMaxDynamicSharedMemorySize, SMEM_GEMM);
        cudaFuncSetAttribute(k_gemm<2>, cudaFuncAttributeMaxDynamicSharedMemorySize, SMEM_GEMM);
        attr_done = true;
    }

    const int NCVT4 = (2048*512 + 128*1024 + 512*1024)/4;
    k_convert_all<<<(NCVT4+255)/256, 256>>>(in_proj_w, gru_w_ih, out_w);

    k_ln<<<MQ, 128>>>(x, norm_w, norm_b);

    k_gemm<0><<<dim3(2048/128, MQ/128), 256, SMEM_GEMM>>>(in_proj_b, nullptr, nullptr);

    k_conv<<<1024, 256>>>(conv_w, conv_b);

    k_gemm<1><<<dim3(1, MQ/128), 256, SMEM_GEMM>>>(gru_b_ih, nullptr, nullptr);

    k_gru<<<BQ, 32>>>(gru_w_hh, gru_b_hh);

    k_ssm<<<(MQ*(EQ/8)+255)/256, 256>>>(ssm_w, ssm_b);

    k_gemm<2><<<dim3(512/128, MQ/128), 256, SMEM_GEMM>>>(out_b, x, out);
}